// round 14
// baseline (speedup 1.0000x reference)
#include <cuda_runtime.h>
#include <cuda_bf16.h>
#include <stdint.h>

#ifndef CLAMP_VAL
#define CLAMP_VAL 10000.0f
#endif

__device__ __forceinline__ float clampv(float v) {
    return fminf(fmaxf(v, -CLAMP_VAL), CLAMP_VAL);
}

// ---------------------------------------------------------------------------
// Fast path: in_w = 8192, out_w = 8191. One block per row, TPB=256.
// Aligned LDG.128 + aligned STG.128; per-row 4-byte phase (lead = row & 3).
// Overlap components come from lane t+1 via __shfl_down_sync (R13 win:
// 38.66us vs 39.78us for the dual-load version). R14 reduces register
// pressure to recover occupancy: no index clamp (max v = 2047 provably
// in-row), one unified predicated LDG.128 for lane-31 fixup, and
// __launch_bounds__(256, 8) pinning regs <= 32.
// ---------------------------------------------------------------------------
constexpr int TPB = 256;

__global__ void __launch_bounds__(TPB, 8)
binagg_row_kernel(const float4* __restrict__ x4, float* __restrict__ out)
{
    const unsigned r = blockIdx.x;
    const float4* xrow = x4 + (size_t)r * 2048u;           // 8192 floats / 4
    const float*  xs   = (const float*)xrow;
    float*        orow = out + (size_t)r * 8191u;
    const int tid  = threadIdx.x;
    const bool last_lane = ((tid & 31) == 31);
    const int lead = (int)(r & 3u);                         // out-row phase

    // Head: cols 0..lead-1 (0..3 scalars)
    if (tid < lead) orow[tid] = clampv(__ldg(xs + tid));

    // Aligned out-vectors covering cols [lead, lead+4*count), max col <= 8189
    const int count = ((8186 - lead) >> 2) + 1;             // 2047 or 2046
    float4* ov = (float4*)(orow + lead);                    // 16B aligned

    if (lead == 0) {
        #pragma unroll 4
        for (int v = tid; v < count; v += TPB) {
            float4 a = __ldg(&xrow[v]);
            float4 s = { clampv(a.x), clampv(a.y), clampv(a.z), clampv(a.w) };
            __stcs(&ov[v], s);
        }
    } else {
        // Uniform 8 iterations; every lane loads (v <= 2047 always in-row),
        // shuffles run fully converged, stores predicated on v < count.
        #pragma unroll 8
        for (int k = 0; k < 8; ++k) {
            int v = tid + k * TPB;                          // <= 2047
            bool active = (v < count);
            float4 a  = __ldg(&xrow[v]);
            float  bx = __shfl_down_sync(0xFFFFFFFFu, a.x, 1);
            float  by = __shfl_down_sync(0xFFFFFFFFu, a.y, 1);
            float  bz = __shfl_down_sync(0xFFFFFFFFu, a.z, 1);
            if (last_lane & active) {                       // v+1 <= 2047 when active
                float4 b = __ldg(&xrow[v + 1]);
                bx = b.x; by = b.y; bz = b.z;
            }
            if (active) {
                float4 s;
                if (lead == 1)      { s.x = a.y; s.y = a.z; s.z = a.w; s.w = bx; }
                else if (lead == 2) { s.x = a.z; s.y = a.w; s.z = bx;  s.w = by; }
                else                { s.x = a.w; s.y = bx;  s.z = by;  s.w = bz; }
                s.x = clampv(s.x); s.y = clampv(s.y);
                s.z = clampv(s.z); s.w = clampv(s.w);
                __stcs(&ov[v], s);
            }
        }
    }

    // Tail: cols [lead + 4*count, 8190]; col 8190 = mean of last two inputs
    const int tstart = lead + 4 * count;
    for (int c = tstart + tid; c <= 8190; c += TPB) {
        float val = (c == 8190)
                  ? 0.5f * (__ldg(xs + 8190) + __ldg(xs + 8191))
                  : __ldg(xs + c);
        orow[c] = clampv(val);
    }
}

// ---------------------------------------------------------------------------
// Generic fallback (any in_w/out_w): flat output indexing, scalar.
// ---------------------------------------------------------------------------
__global__ void __launch_bounds__(256)
binagg_generic_kernel(const float* __restrict__ x, float* __restrict__ out,
                      int in_w, int out_w, unsigned total)
{
    unsigned oo = blockIdx.x * blockDim.x + threadIdx.x;
    if (oo >= total) return;
    unsigned r = oo / (unsigned)out_w;
    unsigned c = oo - r * (unsigned)out_w;
    const float* xr = x + (size_t)r * (size_t)in_w;
    float val;
    if (c < (unsigned)(out_w - 1)) {
        val = __ldg(xr + c);
    } else {
        float s = 0.0f;
        for (int k = out_w - 1; k < in_w; ++k) s += __ldg(xr + k);
        val = s / (float)(in_w - out_w + 1);
    }
    out[oo] = clampv(val);
}

extern "C" void kernel_launch(void* const* d_in, const int* in_sizes, int n_in,
                              void* d_out, int out_size)
{
    const float* x = (const float*)d_in[0];
    float* out = (float*)d_out;

    const int in_w = 8192;
    int batch = in_sizes[0] / in_w;
    int out_w = (batch > 0) ? out_size / batch : 0;

    bool fast = (batch > 0) &&
                (batch * in_w == in_sizes[0]) &&
                (out_w == in_w - 1) &&
                ((size_t)batch * (size_t)out_w == (size_t)out_size);

    if (fast) {
        binagg_row_kernel<<<batch, TPB>>>((const float4*)x, out);
    } else {
        int iw = in_sizes[0];
        int ow = out_size;
        for (int cand = 8192; cand >= 1; cand >>= 1) {
            if (in_sizes[0] % cand == 0) {
                int bb = in_sizes[0] / cand;
                if (bb > 0 && out_size % bb == 0) { iw = cand; ow = out_size / bb; break; }
            }
        }
        unsigned total = (unsigned)out_size;
        unsigned blocks = (total + 255) / 256;
        binagg_generic_kernel<<<blocks, 256>>>(x, out, iw, ow, total);
    }
}

// round 15
// speedup vs baseline: 1.0307x; 1.0307x over previous
#include <cuda_runtime.h>
#include <cuda_bf16.h>
#include <stdint.h>

#ifndef CLAMP_VAL
#define CLAMP_VAL 10000.0f
#endif

__device__ __forceinline__ float clampv(float v) {
    return fminf(fmaxf(v, -CLAMP_VAL), CLAMP_VAL);
}

// ---------------------------------------------------------------------------
// Fast path: in_w = 8192, out_w = 8191. One block per row, TPB=256.
// Aligned LDG.128 + aligned STG.128; per-row 4-byte phase (lead = row & 3).
// Overlap components come from lane t+1 via __shfl_down_sync.
// R13 configuration (measured 38.66us — best) reproduced verbatim, minus the
// provably-dead min(v,2047) clamp (max v = 255 + 7*256 = 2047, always
// in-row). Lead-specialized loops, unroll 4, mixed-width lane-31 fixup,
// NO launch-bounds reg cap: R14 showed the extra registers carry useful
// in-flight loads (regs 32 / occ 81% version was SLOWER at 39.87us).
// ---------------------------------------------------------------------------
constexpr int TPB = 256;

__global__ void __launch_bounds__(TPB)
binagg_row_kernel(const float4* __restrict__ x4, float* __restrict__ out)
{
    const unsigned r = blockIdx.x;
    const float4* xrow = x4 + (size_t)r * 2048u;           // 8192 floats / 4
    const float*  xs   = (const float*)xrow;
    const float2* xs2  = (const float2*)xrow;
    float*        orow = out + (size_t)r * 8191u;
    const int tid  = threadIdx.x;
    const int lane = tid & 31;
    const bool last_lane = (lane == 31);
    const int lead = (int)(r & 3u);                         // out-row phase

    // Head: cols 0..lead-1 (0..3 scalars)
    if (tid < lead) orow[tid] = clampv(__ldg(xs + tid));

    // Aligned out-vectors covering cols [lead, lead+4*count), max col <= 8189
    const int count = ((8186 - lead) >> 2) + 1;             // 2047 or 2046
    float4* ov = (float4*)(orow + lead);                    // 16B aligned
    const int n_iter = (count + TPB - 1) / TPB;             // uniform: 8

    if (lead == 0) {
        #pragma unroll 4
        for (int v = tid; v < count; v += TPB) {
            float4 a = __ldg(&xrow[v]);
            float4 s = { clampv(a.x), clampv(a.y), clampv(a.z), clampv(a.w) };
            __stcs(&ov[v], s);
        }
    } else if (lead == 1) {
        #pragma unroll 4
        for (int k = 0; k < n_iter; ++k) {
            int v = tid + k * TPB;                          // <= 2047, in-row
            bool active = (v < count);
            float4 a  = __ldg(&xrow[v]);
            float  bx = __shfl_down_sync(0xFFFFFFFFu, a.x, 1);
            if (last_lane && active) bx = __ldg(xs + 4 * v + 4);
            if (active) {
                float4 s = { clampv(a.y), clampv(a.z), clampv(a.w), clampv(bx) };
                __stcs(&ov[v], s);
            }
        }
    } else if (lead == 2) {
        #pragma unroll 4
        for (int k = 0; k < n_iter; ++k) {
            int v = tid + k * TPB;
            bool active = (v < count);
            float4 a  = __ldg(&xrow[v]);
            float  bx = __shfl_down_sync(0xFFFFFFFFu, a.x, 1);
            float  by = __shfl_down_sync(0xFFFFFFFFu, a.y, 1);
            if (last_lane && active) {
                float2 b = __ldg(&xs2[2 * v + 2]);
                bx = b.x; by = b.y;
            }
            if (active) {
                float4 s = { clampv(a.z), clampv(a.w), clampv(bx), clampv(by) };
                __stcs(&ov[v], s);
            }
        }
    } else {
        #pragma unroll 4
        for (int k = 0; k < n_iter; ++k) {
            int v = tid + k * TPB;
            bool active = (v < count);
            float4 a  = __ldg(&xrow[v]);
            float  bx = __shfl_down_sync(0xFFFFFFFFu, a.x, 1);
            float  by = __shfl_down_sync(0xFFFFFFFFu, a.y, 1);
            float  bz = __shfl_down_sync(0xFFFFFFFFu, a.z, 1);
            if (last_lane && active) {
                float2 b = __ldg(&xs2[2 * v + 2]);
                bx = b.x; by = b.y;
                bz = __ldg(xs + 4 * v + 6);
            }
            if (active) {
                float4 s = { clampv(a.w), clampv(bx), clampv(by), clampv(bz) };
                __stcs(&ov[v], s);
            }
        }
    }

    // Tail: cols [lead + 4*count, 8190]; col 8190 = mean of last two inputs
    const int tstart = lead + 4 * count;
    for (int c = tstart + tid; c <= 8190; c += TPB) {
        float val = (c == 8190)
                  ? 0.5f * (__ldg(xs + 8190) + __ldg(xs + 8191))
                  : __ldg(xs + c);
        orow[c] = clampv(val);
    }
}

// ---------------------------------------------------------------------------
// Generic fallback (any in_w/out_w): flat output indexing, scalar.
// ---------------------------------------------------------------------------
__global__ void __launch_bounds__(256)
binagg_generic_kernel(const float* __restrict__ x, float* __restrict__ out,
                      int in_w, int out_w, unsigned total)
{
    unsigned oo = blockIdx.x * blockDim.x + threadIdx.x;
    if (oo >= total) return;
    unsigned r = oo / (unsigned)out_w;
    unsigned c = oo - r * (unsigned)out_w;
    const float* xr = x + (size_t)r * (size_t)in_w;
    float val;
    if (c < (unsigned)(out_w - 1)) {
        val = __ldg(xr + c);
    } else {
        float s = 0.0f;
        for (int k = out_w - 1; k < in_w; ++k) s += __ldg(xr + k);
        val = s / (float)(in_w - out_w + 1);
    }
    out[oo] = clampv(val);
}

extern "C" void kernel_launch(void* const* d_in, const int* in_sizes, int n_in,
                              void* d_out, int out_size)
{
    const float* x = (const float*)d_in[0];
    float* out = (float*)d_out;

    const int in_w = 8192;
    int batch = in_sizes[0] / in_w;
    int out_w = (batch > 0) ? out_size / batch : 0;

    bool fast = (batch > 0) &&
                (batch * in_w == in_sizes[0]) &&
                (out_w == in_w - 1) &&
                ((size_t)batch * (size_t)out_w == (size_t)out_size);

    if (fast) {
        binagg_row_kernel<<<batch, TPB>>>((const float4*)x, out);
    } else {
        int iw = in_sizes[0];
        int ow = out_size;
        for (int cand = 8192; cand >= 1; cand >>= 1) {
            if (in_sizes[0] % cand == 0) {
                int bb = in_sizes[0] / cand;
                if (bb > 0 && out_size % bb == 0) { iw = cand; ow = out_size / bb; break; }
            }
        }
        unsigned total = (unsigned)out_size;
        unsigned blocks = (total + 255) / 256;
        binagg_generic_kernel<<<blocks, 256>>>(x, out, iw, ow, total);
    }
}

// round 16
// speedup vs baseline: 1.0358x; 1.0049x over previous
#include <cuda_runtime.h>
#include <cuda_bf16.h>
#include <stdint.h>

#ifndef CLAMP_VAL
#define CLAMP_VAL 10000.0f
#endif

__device__ __forceinline__ float clampv(float v) {
    return fminf(fmaxf(v, -CLAMP_VAL), CLAMP_VAL);
}

// ---------------------------------------------------------------------------
// Fast path: in_w = 8192, out_w = 8191. One block per row, TPB=256.
// Aligned LDG.128 + aligned STG.128; per-row 4-byte phase (lead = row & 3).
// Overlap components come from lane t+1 via __shfl_down_sync (R13/R15 win:
// 38.7us vs 39.8us dual-load). R16 single-variable change vs R15:
// full unroll (8) on the shuffle loops to front-batch all 8 independent
// a-loads per thread (ILP > occupancy in this regime, per R13-vs-R14).
// ---------------------------------------------------------------------------
constexpr int TPB = 256;

__global__ void __launch_bounds__(TPB)
binagg_row_kernel(const float4* __restrict__ x4, float* __restrict__ out)
{
    const unsigned r = blockIdx.x;
    const float4* xrow = x4 + (size_t)r * 2048u;           // 8192 floats / 4
    const float*  xs   = (const float*)xrow;
    const float2* xs2  = (const float2*)xrow;
    float*        orow = out + (size_t)r * 8191u;
    const int tid  = threadIdx.x;
    const int lane = tid & 31;
    const bool last_lane = (lane == 31);
    const int lead = (int)(r & 3u);                         // out-row phase

    // Head: cols 0..lead-1 (0..3 scalars)
    if (tid < lead) orow[tid] = clampv(__ldg(xs + tid));

    // Aligned out-vectors covering cols [lead, lead+4*count), max col <= 8189
    const int count = ((8186 - lead) >> 2) + 1;             // 2047 or 2046
    float4* ov = (float4*)(orow + lead);                    // 16B aligned

    if (lead == 0) {
        #pragma unroll 4
        for (int v = tid; v < count; v += TPB) {
            float4 a = __ldg(&xrow[v]);
            float4 s = { clampv(a.x), clampv(a.y), clampv(a.z), clampv(a.w) };
            __stcs(&ov[v], s);
        }
    } else if (lead == 1) {
        #pragma unroll 8
        for (int k = 0; k < 8; ++k) {
            int v = tid + k * TPB;                          // <= 2047, in-row
            bool active = (v < count);
            float4 a  = __ldg(&xrow[v]);
            float  bx = __shfl_down_sync(0xFFFFFFFFu, a.x, 1);
            if (last_lane && active) bx = __ldg(xs + 4 * v + 4);
            if (active) {
                float4 s = { clampv(a.y), clampv(a.z), clampv(a.w), clampv(bx) };
                __stcs(&ov[v], s);
            }
        }
    } else if (lead == 2) {
        #pragma unroll 8
        for (int k = 0; k < 8; ++k) {
            int v = tid + k * TPB;
            bool active = (v < count);
            float4 a  = __ldg(&xrow[v]);
            float  bx = __shfl_down_sync(0xFFFFFFFFu, a.x, 1);
            float  by = __shfl_down_sync(0xFFFFFFFFu, a.y, 1);
            if (last_lane && active) {
                float2 b = __ldg(&xs2[2 * v + 2]);
                bx = b.x; by = b.y;
            }
            if (active) {
                float4 s = { clampv(a.z), clampv(a.w), clampv(bx), clampv(by) };
                __stcs(&ov[v], s);
            }
        }
    } else {
        #pragma unroll 8
        for (int k = 0; k < 8; ++k) {
            int v = tid + k * TPB;
            bool active = (v < count);
            float4 a  = __ldg(&xrow[v]);
            float  bx = __shfl_down_sync(0xFFFFFFFFu, a.x, 1);
            float  by = __shfl_down_sync(0xFFFFFFFFu, a.y, 1);
            float  bz = __shfl_down_sync(0xFFFFFFFFu, a.z, 1);
            if (last_lane && active) {
                float2 b = __ldg(&xs2[2 * v + 2]);
                bx = b.x; by = b.y;
                bz = __ldg(xs + 4 * v + 6);
            }
            if (active) {
                float4 s = { clampv(a.w), clampv(bx), clampv(by), clampv(bz) };
                __stcs(&ov[v], s);
            }
        }
    }

    // Tail: cols [lead + 4*count, 8190]; col 8190 = mean of last two inputs
    const int tstart = lead + 4 * count;
    for (int c = tstart + tid; c <= 8190; c += TPB) {
        float val = (c == 8190)
                  ? 0.5f * (__ldg(xs + 8190) + __ldg(xs + 8191))
                  : __ldg(xs + c);
        orow[c] = clampv(val);
    }
}

// ---------------------------------------------------------------------------
// Generic fallback (any in_w/out_w): flat output indexing, scalar.
// ---------------------------------------------------------------------------
__global__ void __launch_bounds__(256)
binagg_generic_kernel(const float* __restrict__ x, float* __restrict__ out,
                      int in_w, int out_w, unsigned total)
{
    unsigned oo = blockIdx.x * blockDim.x + threadIdx.x;
    if (oo >= total) return;
    unsigned r = oo / (unsigned)out_w;
    unsigned c = oo - r * (unsigned)out_w;
    const float* xr = x + (size_t)r * (size_t)in_w;
    float val;
    if (c < (unsigned)(out_w - 1)) {
        val = __ldg(xr + c);
    } else {
        float s = 0.0f;
        for (int k = out_w - 1; k < in_w; ++k) s += __ldg(xr + k);
        val = s / (float)(in_w - out_w + 1);
    }
    out[oo] = clampv(val);
}

extern "C" void kernel_launch(void* const* d_in, const int* in_sizes, int n_in,
                              void* d_out, int out_size)
{
    const float* x = (const float*)d_in[0];
    float* out = (float*)d_out;

    const int in_w = 8192;
    int batch = in_sizes[0] / in_w;
    int out_w = (batch > 0) ? out_size / batch : 0;

    bool fast = (batch > 0) &&
                (batch * in_w == in_sizes[0]) &&
                (out_w == in_w - 1) &&
                ((size_t)batch * (size_t)out_w == (size_t)out_size);

    if (fast) {
        binagg_row_kernel<<<batch, TPB>>>((const float4*)x, out);
    } else {
        int iw = in_sizes[0];
        int ow = out_size;
        for (int cand = 8192; cand >= 1; cand >>= 1) {
            if (in_sizes[0] % cand == 0) {
                int bb = in_sizes[0] / cand;
                if (bb > 0 && out_size % bb == 0) { iw = cand; ow = out_size / bb; break; }
            }
        }
        unsigned total = (unsigned)out_size;
        unsigned blocks = (total + 255) / 256;
        binagg_generic_kernel<<<blocks, 256>>>(x, out, iw, ow, total);
    }
}

// round 17
// speedup vs baseline: 1.0365x; 1.0007x over previous
#include <cuda_runtime.h>
#include <cuda_bf16.h>
#include <stdint.h>

#ifndef CLAMP_VAL
#define CLAMP_VAL 10000.0f
#endif

__device__ __forceinline__ float clampv(float v) {
    return fminf(fmaxf(v, -CLAMP_VAL), CLAMP_VAL);
}

// ---------------------------------------------------------------------------
// Fast path: in_w = 8192, out_w = 8191. One block per row, TPB=256.
// Aligned LDG.128 + aligned STG.128; per-row 4-byte phase (lead = row & 3).
// Overlap components come from lane t+1 via __shfl_down_sync.
// R16 (38.46us best): full unroll 8 on shuffle loops front-batches all 8
// independent a-loads per thread. R17 single-variable change: the lead==0
// copy path gets the same uniform fully-unrolled 8-iteration shape.
// ---------------------------------------------------------------------------
constexpr int TPB = 256;

__global__ void __launch_bounds__(TPB)
binagg_row_kernel(const float4* __restrict__ x4, float* __restrict__ out)
{
    const unsigned r = blockIdx.x;
    const float4* xrow = x4 + (size_t)r * 2048u;           // 8192 floats / 4
    const float*  xs   = (const float*)xrow;
    const float2* xs2  = (const float2*)xrow;
    float*        orow = out + (size_t)r * 8191u;
    const int tid  = threadIdx.x;
    const int lane = tid & 31;
    const bool last_lane = (lane == 31);
    const int lead = (int)(r & 3u);                         // out-row phase

    // Head: cols 0..lead-1 (0..3 scalars)
    if (tid < lead) orow[tid] = clampv(__ldg(xs + tid));

    // Aligned out-vectors covering cols [lead, lead+4*count), max col <= 8189
    const int count = ((8186 - lead) >> 2) + 1;             // 2047 or 2046
    float4* ov = (float4*)(orow + lead);                    // 16B aligned

    if (lead == 0) {
        #pragma unroll 8
        for (int k = 0; k < 8; ++k) {
            int v = tid + k * TPB;                          // <= 2047, in-row
            bool active = (v < count);                      // count = 2047 here
            float4 a = __ldg(&xrow[v]);
            if (active) {
                float4 s = { clampv(a.x), clampv(a.y), clampv(a.z), clampv(a.w) };
                __stcs(&ov[v], s);
            }
        }
    } else if (lead == 1) {
        #pragma unroll 8
        for (int k = 0; k < 8; ++k) {
            int v = tid + k * TPB;                          // <= 2047, in-row
            bool active = (v < count);
            float4 a  = __ldg(&xrow[v]);
            float  bx = __shfl_down_sync(0xFFFFFFFFu, a.x, 1);
            if (last_lane && active) bx = __ldg(xs + 4 * v + 4);
            if (active) {
                float4 s = { clampv(a.y), clampv(a.z), clampv(a.w), clampv(bx) };
                __stcs(&ov[v], s);
            }
        }
    } else if (lead == 2) {
        #pragma unroll 8
        for (int k = 0; k < 8; ++k) {
            int v = tid + k * TPB;
            bool active = (v < count);
            float4 a  = __ldg(&xrow[v]);
            float  bx = __shfl_down_sync(0xFFFFFFFFu, a.x, 1);
            float  by = __shfl_down_sync(0xFFFFFFFFu, a.y, 1);
            if (last_lane && active) {
                float2 b = __ldg(&xs2[2 * v + 2]);
                bx = b.x; by = b.y;
            }
            if (active) {
                float4 s = { clampv(a.z), clampv(a.w), clampv(bx), clampv(by) };
                __stcs(&ov[v], s);
            }
        }
    } else {
        #pragma unroll 8
        for (int k = 0; k < 8; ++k) {
            int v = tid + k * TPB;
            bool active = (v < count);
            float4 a  = __ldg(&xrow[v]);
            float  bx = __shfl_down_sync(0xFFFFFFFFu, a.x, 1);
            float  by = __shfl_down_sync(0xFFFFFFFFu, a.y, 1);
            float  bz = __shfl_down_sync(0xFFFFFFFFu, a.z, 1);
            if (last_lane && active) {
                float2 b = __ldg(&xs2[2 * v + 2]);
                bx = b.x; by = b.y;
                bz = __ldg(xs + 4 * v + 6);
            }
            if (active) {
                float4 s = { clampv(a.w), clampv(bx), clampv(by), clampv(bz) };
                __stcs(&ov[v], s);
            }
        }
    }

    // Tail: cols [lead + 4*count, 8190]; col 8190 = mean of last two inputs
    const int tstart = lead + 4 * count;
    for (int c = tstart + tid; c <= 8190; c += TPB) {
        float val = (c == 8190)
                  ? 0.5f * (__ldg(xs + 8190) + __ldg(xs + 8191))
                  : __ldg(xs + c);
        orow[c] = clampv(val);
    }
}

// ---------------------------------------------------------------------------
// Generic fallback (any in_w/out_w): flat output indexing, scalar.
// ---------------------------------------------------------------------------
__global__ void __launch_bounds__(256)
binagg_generic_kernel(const float* __restrict__ x, float* __restrict__ out,
                      int in_w, int out_w, unsigned total)
{
    unsigned oo = blockIdx.x * blockDim.x + threadIdx.x;
    if (oo >= total) return;
    unsigned r = oo / (unsigned)out_w;
    unsigned c = oo - r * (unsigned)out_w;
    const float* xr = x + (size_t)r * (size_t)in_w;
    float val;
    if (c < (unsigned)(out_w - 1)) {
        val = __ldg(xr + c);
    } else {
        float s = 0.0f;
        for (int k = out_w - 1; k < in_w; ++k) s += __ldg(xr + k);
        val = s / (float)(in_w - out_w + 1);
    }
    out[oo] = clampv(val);
}

extern "C" void kernel_launch(void* const* d_in, const int* in_sizes, int n_in,
                              void* d_out, int out_size)
{
    const float* x = (const float*)d_in[0];
    float* out = (float*)d_out;

    const int in_w = 8192;
    int batch = in_sizes[0] / in_w;
    int out_w = (batch > 0) ? out_size / batch : 0;

    bool fast = (batch > 0) &&
                (batch * in_w == in_sizes[0]) &&
                (out_w == in_w - 1) &&
                ((size_t)batch * (size_t)out_w == (size_t)out_size);

    if (fast) {
        binagg_row_kernel<<<batch, TPB>>>((const float4*)x, out);
    } else {
        int iw = in_sizes[0];
        int ow = out_size;
        for (int cand = 8192; cand >= 1; cand >>= 1) {
            if (in_sizes[0] % cand == 0) {
                int bb = in_sizes[0] / cand;
                if (bb > 0 && out_size % bb == 0) { iw = cand; ow = out_size / bb; break; }
            }
        }
        unsigned total = (unsigned)out_size;
        unsigned blocks = (total + 255) / 256;
        binagg_generic_kernel<<<blocks, 256>>>(x, out, iw, ow, total);
    }
}